// round 1
// baseline (speedup 1.0000x reference)
#include <cuda_runtime.h>
#include <math.h>

#define DAYS  365
#define NY    30
#define SGRID 4000
#define TT    (DAYS * NY)
#define NPAIR 435
#define NQ    5
#define K1_SER 16

#define POSINF __int_as_float(0x7f800000)
#define FULLM  0xffffffffu

// ---------------- intermediate storage (no allocations allowed) -------------
__device__ float  g_pM[SGRID * NY];
__device__ float  g_tM[SGRID * NY];
__device__ float  g_pQ[SGRID * NQ * NY];
__device__ float  g_tQ[SGRID * NQ * NY];
__device__ double g_sse;
__device__ double g_trend;

// ---------------- warp-level bitonic sort of 512 (16 regs/lane) -------------
// element global index g = (r<<5) | lane ; ascending result
__device__ __forceinline__ void bitonic512(float v[16], int lane) {
#pragma unroll
    for (int m = 2; m <= 512; m <<= 1) {
        // register-register phases (stride >= 32)
#pragma unroll
        for (int j = 256; j >= 32; j >>= 1) {
            if (j < m) {
                int rj = j >> 5;
#pragma unroll
                for (int r = 0; r < 16; r++) {
                    if ((r & rj) == 0) {
                        int r2 = r | rj;
                        bool up = (((r << 5) & m) == 0);
                        float a = v[r], b = v[r2];
                        float lo = fminf(a, b), hi = fmaxf(a, b);
                        v[r]  = up ? lo : hi;
                        v[r2] = up ? hi : lo;
                    }
                }
            }
        }
        // cross-lane phases (stride <= 16)
#pragma unroll
        for (int j = 16; j >= 1; j >>= 1) {
            if (j < m) {
#pragma unroll
                for (int r = 0; r < 16; r++) {
                    bool up = ((((r << 5) | lane) & m) == 0);
                    float other = __shfl_xor_sync(FULLM, v[r], j);
                    bool lower = ((lane & j) == 0);
                    v[r] = (up == lower) ? fminf(v[r], other) : fmaxf(v[r], other);
                }
            }
        }
    }
}

// ---------------- kernel 0: zero accumulators --------------------------------
__global__ void k_zero() {
    g_sse = 0.0;
    g_trend = 0.0;
}

// ---------------- kernel 1: transpose + SSE + per-(series,year) sort ---------
// grid (SGRID/K1_SER, NY), block 512 (16 warps, 1 warp per series)
__global__ __launch_bounds__(512) void k_sortdays(const float* __restrict__ pred,
                                                  const float* __restrict__ obs) {
    __shared__ float shP[K1_SER][DAYS];
    __shared__ float shT[K1_SER][DAYS];
    __shared__ float warpsum[16];

    int y      = blockIdx.y;
    int s_base = blockIdx.x * K1_SER;
    int tid    = threadIdx.x;
    int w      = tid >> 5;
    int lane   = tid & 31;

    const float* pbase = pred + y * DAYS * SGRID + s_base;
    const float* tbase = obs  + y * DAYS * SGRID + s_base;

    // coalesced load + transpose + fused SSE
    float sse = 0.0f;
    for (int idx = tid; idx < DAYS * K1_SER; idx += 512) {
        int d  = idx >> 4;
        int sl = idx & 15;
        float a = pbase[d * SGRID + sl];
        float b = tbase[d * SGRID + sl];
        shP[sl][d] = a;
        shT[sl][d] = b;
        float df = a - b;
        sse += df * df;
    }
#pragma unroll
    for (int o = 16; o > 0; o >>= 1) sse += __shfl_down_sync(FULLM, sse, o);
    if (lane == 0) warpsum[w] = sse;
    __syncthreads();
    if (tid == 0) {
        float tot = 0.0f;
#pragma unroll
        for (int i = 0; i < 16; i++) tot += warpsum[i];
        atomicAdd(&g_sse, (double)tot);
    }

    int s = s_base + w;

#pragma unroll 1
    for (int pass = 0; pass < 2; pass++) {
        float (*sh)[DAYS] = pass ? shT : shP;
        float* outM = pass ? g_tM : g_pM;
        float* outQ = pass ? g_tQ : g_pQ;

        float v[16];
        float msum = 0.0f;
#pragma unroll
        for (int r = 0; r < 16; r++) {
            int g = (r << 5) | lane;
            if (g < DAYS) { v[r] = sh[w][g]; msum += v[r]; }
            else          { v[r] = POSINF; }
        }
        // yearly mean
#pragma unroll
        for (int o = 16; o > 0; o >>= 1) msum += __shfl_down_sync(FULLM, msum, o);
        if (lane == 0) outM[s * NY + y] = msum / (float)DAYS;

        bitonic512(v, lane);

        // order statistics: ranks 364,357,182,109,7 -> (reg, lane)
        if (lane == 12) outQ[(s * NQ + 0) * NY + y] = v[11];   // g=364
        if (lane == 5)  outQ[(s * NQ + 1) * NY + y] = v[11];   // g=357
        if (lane == 22) outQ[(s * NQ + 2) * NY + y] = v[5];    // g=182
        if (lane == 13) outQ[(s * NQ + 3) * NY + y] = v[3];    // g=109
        if (lane == 7)  outQ[(s * NQ + 4) * NY + y] = v[0];    // g=7
    }
}

// ---------------- kernel 2: Theil-Sen medians + trend terms ------------------
// grid SGRID, block 192 (6 warps: warp0 = mean, warps 1..5 = quantiles)
__global__ __launch_bounds__(192) void k_theil() {
    __shared__ float xs[6][2][NY];

    int s    = blockIdx.x;
    int w    = threadIdx.x >> 5;
    int lane = threadIdx.x & 31;

    const float* xp;
    const float* xt;
    if (w == 0) { xp = g_pM + s * NY;                 xt = g_tM + s * NY; }
    else        { xp = g_pQ + (s * NQ + (w - 1)) * NY; xt = g_tQ + (s * NQ + (w - 1)) * NY; }
    if (lane < NY) {
        xs[w][0][lane] = xp[lane];
        xs[w][1][lane] = xt[lane];
    }
    __syncwarp();

    float med[2];
#pragma unroll 1
    for (int pass = 0; pass < 2; pass++) {
        float v[16];
#pragma unroll
        for (int r = 0; r < 16; r++) {
            int p = (r << 5) | lane;
            if (p < NPAIR) {
                // decode pair index -> (i, j), i<j  (order irrelevant for median)
                int i = 0, rem = p, cnt = NY - 1;
                while (rem >= cnt) { rem -= cnt; i++; cnt--; }
                int j = i + 1 + rem;
                v[r] = (xs[w][pass][j] - xs[w][pass][i]) / (float)(j - i);
            } else {
                v[r] = POSINF;
            }
        }
        bitonic512(v, lane);
        // median of 435 = element 217 -> reg 6, lane 25
        med[pass] = __shfl_sync(FULLM, v[6], 25);
    }

    if (lane == 0) {
        float sp = med[0], st = med[1];
        double term;
        if (w == 0) { float d = st - sp;  term = (double)d * (double)d; }
        else        { float q = st / (-sp); term = (double)q * (double)q; }
        atomicAdd(&g_trend, term);
    }
}

// ---------------- kernel 3: finalize -----------------------------------------
__global__ void k_final(float* out) {
    double mse = g_sse / ((double)TT * (double)SGRID);
    out[0] = (float)(sqrt(mse) + g_trend / (double)SGRID);
}

// ---------------- launch ------------------------------------------------------
extern "C" void kernel_launch(void* const* d_in, const int* in_sizes, int n_in,
                              void* d_out, int out_size) {
    const float* y_pred = (const float*)d_in[0];
    const float* y_obs  = (const float*)d_in[1];
    float* out = (float*)d_out;

    k_zero<<<1, 1>>>();
    k_sortdays<<<dim3(SGRID / K1_SER, NY), 512>>>(y_pred, y_obs);
    k_theil<<<SGRID, 192>>>();
    k_final<<<1, 1>>>(out);
}